// round 12
// baseline (speedup 1.0000x reference)
#include <cuda_runtime.h>
#include <cuda_fp16.h>
#include <cstdint>

// Problem constants
#define Bb  2
#define Ll  2048
#define Dd  2048
#define NHh 16
#define HDh 128
#define Mtot (Bb * Ll)   // 4096

// Scratch (static device globals: allocation-free per harness rules)
__device__ __half g_qkvh[(size_t)Mtot * 3 * Dd];   // 50 MB (fp16 QKV)
__device__ __half g_xh  [(size_t)Mtot * Dd];       // 16 MB
__device__ __half g_wqt [(size_t)3 * Dd * Dd];     // 24 MB (W_qkv^T, K-major)
__device__ __half g_wot [(size_t)Dd * Dd];         //  8 MB (W_out^T, K-major)
__device__ __half g_oh  [(size_t)Mtot * Dd];       // 16 MB (attention O)

// ===========================================================================
// helpers
// ===========================================================================
__device__ __forceinline__ uint32_t smem_u32(const void* p) {
    return (uint32_t)__cvta_generic_to_shared(p);
}
__device__ __forceinline__ void ldsm_x4(uint32_t& r0, uint32_t& r1,
                                        uint32_t& r2, uint32_t& r3, uint32_t addr) {
    asm volatile("ldmatrix.sync.aligned.m8n8.x4.shared.b16 {%0,%1,%2,%3}, [%4];"
                 : "=r"(r0), "=r"(r1), "=r"(r2), "=r"(r3) : "r"(addr));
}
__device__ __forceinline__ void ldsm_x4_t(uint32_t& r0, uint32_t& r1,
                                          uint32_t& r2, uint32_t& r3, uint32_t addr) {
    asm volatile("ldmatrix.sync.aligned.m8n8.x4.trans.shared.b16 {%0,%1,%2,%3}, [%4];"
                 : "=r"(r0), "=r"(r1), "=r"(r2), "=r"(r3) : "r"(addr));
}
__device__ __forceinline__ void mma_fp16(float (&d)[4], const uint32_t (&a)[4],
                                         const uint32_t b0, const uint32_t b1) {
    asm volatile(
        "mma.sync.aligned.m16n8k16.row.col.f32.f16.f16.f32 "
        "{%0,%1,%2,%3},{%4,%5,%6,%7},{%8,%9},{%0,%1,%2,%3};"
        : "+f"(d[0]), "+f"(d[1]), "+f"(d[2]), "+f"(d[3])
        : "r"(a[0]), "r"(a[1]), "r"(a[2]), "r"(a[3]), "r"(b0), "r"(b1));
}
__device__ __forceinline__ void cp_async16(uint32_t d, const void* g) {
    asm volatile("cp.async.cg.shared.global [%0], [%1], 16;" :: "r"(d), "l"(g) : "memory");
}
__device__ __forceinline__ void cp_commit() {
    asm volatile("cp.async.commit_group;" ::: "memory");
}
template<int n> __device__ __forceinline__ void cp_wait() {
    asm volatile("cp.async.wait_group %0;" :: "n"(n) : "memory");
}
__device__ __forceinline__ uint32_t sw128(uint32_t bo) {   // Swizzle<3,4,3>
    return bo ^ ((bo >> 3) & 0x70);
}

// ===========================================================================
// fused prep kernel: x fp32->fp16 convert + both weight transpose/converts
// 1D grid, range dispatch. blocks: [0,8192) x-convert (256 float4 each),
// [8192,20480) W_qkv 32x32 transpose tiles (192 x 64),
// [20480,24576) W_out 32x32 transpose tiles (64 x 64).
// ===========================================================================
#define PREP_X_BLKS  8192
#define PREP_WQ_BLKS 12288
#define PREP_GRID    24576

__global__ __launch_bounds__(256) void prep_kernel(
    const float* __restrict__ X,  __half* __restrict__ Xh,
    const float* __restrict__ Wq, __half* __restrict__ Wqt,
    const float* __restrict__ Wo, __half* __restrict__ Wot)
{
    __shared__ float t[32][33];
    const int bid = blockIdx.x;
    if (bid < PREP_X_BLKS) {
        size_t i = (size_t)bid * 256 + threadIdx.x;   // float4 index
        float4 v = ((const float4*)X)[i];
        __half2 a = __floats2half2_rn(v.x, v.y);
        __half2 b = __floats2half2_rn(v.z, v.w);
        ((uint2*)Xh)[i] = make_uint2(*(uint32_t*)&a, *(uint32_t*)&b);
        return;
    }
    // transpose job: W [K][N] fp32 -> T [N][K] fp16
    const float* W; __half* T; int N, tile;
    if (bid < PREP_X_BLKS + PREP_WQ_BLKS) {
        W = Wq; T = Wqt; N = 3 * Dd; tile = bid - PREP_X_BLKS;       // 192 x 64
    } else {
        W = Wo; T = Wot; N = Dd;     tile = bid - PREP_X_BLKS - PREP_WQ_BLKS; // 64 x 64
    }
    const int ntiles_n = N / 32;
    const int n0 = (tile % ntiles_n) * 32;
    const int k0 = (tile / ntiles_n) * 32;
    const int c = threadIdx.x & 31, r8 = threadIdx.x >> 5;
#pragma unroll
    for (int i = 0; i < 4; i++) {
        int r = r8 + i * 8;
        t[r][c] = W[(size_t)(k0 + r) * N + n0 + c];
    }
    __syncthreads();
#pragma unroll
    for (int i = 0; i < 4; i++) {
        int r = r8 + i * 8;                      // local n index
        T[(size_t)(n0 + r) * Dd + k0 + c] = __float2half_rn(t[c][r]);  // K = Dd always
    }
}

// ===========================================================================
// fp16 GEMM (mma.sync): C[M,N] = A[M,K] @ B[N,K]^T + bias
// BM=128, BN=128, BK=64. 256 threads = 8 warps (4m x 2n), warp tile 32x64.
// 3-stage cp.async ring, distance-2 prefetch, SINGLE barrier per k-chunk:
//   cp_wait(G_kc) -> barrier (also guards stage (kc-1) readers) ->
//   load stage (kc+2)%3 (== (kc-1)%3, now safe) -> compute(kc).
// 2 CTAs/SM.
// ===========================================================================
#define GBM 128
#define GBN 128
#define GBK 64
#define GA_BYTES (GBM * 128)               // 16384
#define GB_BYTES (GBN * 128)               // 16384
#define GSTAGE_B (GA_BYTES + GB_BYTES)     // 32768
#define GNST 3
#define GEMM_SMEM (GNST * GSTAGE_B)        // 98304

template<bool OUT_HALF>
__global__ __launch_bounds__(256, 2) void gemm_fp16_kernel(
    const __half* __restrict__ A, const __half* __restrict__ Bw,
    const float* __restrict__ bias, void* __restrict__ Cout, int N, int K)
{
    extern __shared__ __align__(1024) uint8_t smem[];
    const uint32_t sb = smem_u32(smem);
    const int tid = threadIdx.x, lane = tid & 31, warp = tid >> 5;
    const int wm = warp >> 1, wn = warp & 1;
    const int row0 = blockIdx.y * GBM, col0 = blockIdx.x * GBN;

    float acc[2][8][4];
#pragma unroll
    for (int mi = 0; mi < 2; mi++)
#pragma unroll
        for (int ni = 0; ni < 8; ni++)
#pragma unroll
            for (int c = 0; c < 4; c++) acc[mi][ni][c] = 0.f;

    auto load_stage = [&](int s, int kc) {
        const uint32_t st = sb + s * GSTAGE_B;
        const int k0 = kc * GBK;
#pragma unroll
        for (int i = 0; i < 4; i++) {          // A: 1024 16B chunks
            int idx = tid + i * 256;
            int r = idx >> 3, c = idx & 7;
            uint32_t bo = (uint32_t)(r * 128 + c * 16);
            cp_async16(st + sw128(bo), A + (size_t)(row0 + r) * K + k0 + c * 8);
        }
#pragma unroll
        for (int i = 0; i < 4; i++) {          // B: 1024 16B chunks
            int idx = tid + i * 256;
            int r = idx >> 3, c = idx & 7;
            uint32_t bo = (uint32_t)(r * 128 + c * 16);
            cp_async16(st + GA_BYTES + sw128(bo),
                       Bw + (size_t)(col0 + r) * K + k0 + c * 8);
        }
    };

    const int lrow = lane & 15;
    const int lcol = (lane >> 4) * 16;         // byte offset of k-chunk

    auto compute = [&](int s) {
        const uint32_t stA = sb + s * GSTAGE_B;
        const uint32_t stB = stA + GA_BYTES;
#pragma unroll
        for (int k16 = 0; k16 < 4; k16++) {
            uint32_t a[2][4];
#pragma unroll
            for (int mi = 0; mi < 2; mi++) {
                uint32_t bo = (uint32_t)((wm * 32 + mi * 16 + lrow) * 128 + k16 * 32 + lcol);
                ldsm_x4(a[mi][0], a[mi][1], a[mi][2], a[mi][3], stA + sw128(bo));
            }
            uint32_t bf[8][2];
#pragma unroll
            for (int nb = 0; nb < 4; nb++) {
                uint32_t bo = (uint32_t)((wn * 64 + nb * 16 + lrow) * 128 + k16 * 32 + lcol);
                uint32_t t0, t1, t2, t3;
                ldsm_x4(t0, t1, t2, t3, stB + sw128(bo));
                bf[2 * nb][0] = t0; bf[2 * nb][1] = t2;      // n8 lo: k0-7,k8-15
                bf[2 * nb + 1][0] = t1; bf[2 * nb + 1][1] = t3;
            }
#pragma unroll
            for (int mi = 0; mi < 2; mi++)
#pragma unroll
                for (int ni = 0; ni < 8; ni++)
                    mma_fp16(acc[mi][ni], a[mi], bf[ni][0], bf[ni][1]);
        }
    };

    const int nKC = K / GBK;                   // 32
    load_stage(0, 0); cp_commit();
    load_stage(1, 1); cp_commit();

    for (int kc = 0; kc < nKC; kc++) {
        if (kc + 2 < nKC) cp_wait<1>();        // G(kc) done, G(kc+1) may fly
        else              cp_wait<0>();        // tail: drain everything
        __syncthreads();                       // data visible + stage (kc-1) free
        if (kc + 2 < nKC) { load_stage((kc + 2) % GNST, kc + 2); cp_commit(); }
        compute(kc % GNST);
    }

    // Epilogue
    const int g  = lane >> 2;
    const int i2 = (lane & 3) * 2;
#pragma unroll
    for (int mi = 0; mi < 2; mi++) {
#pragma unroll
        for (int ni = 0; ni < 8; ni++) {
            int col = col0 + wn * 64 + ni * 8 + i2;
            float bx = bias[col], by = bias[col + 1];
            int r_top = row0 + wm * 32 + mi * 16 + g;
            float v0 = acc[mi][ni][0] + bx, v1 = acc[mi][ni][1] + by;
            float v2 = acc[mi][ni][2] + bx, v3 = acc[mi][ni][3] + by;
            if (OUT_HALF) {
                __half* C = (__half*)Cout;
                __half2 p0 = __floats2half2_rn(v0, v1);
                __half2 p1 = __floats2half2_rn(v2, v3);
                *(__half2*)(C + (size_t)r_top * N + col)       = p0;
                *(__half2*)(C + (size_t)(r_top + 8) * N + col) = p1;
            } else {
                float* C = (float*)Cout;
                *(float2*)(C + (size_t)r_top * N + col)       = make_float2(v0, v1);
                *(float2*)(C + (size_t)(r_top + 8) * N + col) = make_float2(v2, v3);
            }
        }
    }
}

// ===========================================================================
// Flash attention, fp16 MMA. cp.async Q/V double buffer, 2 CTAs/SM,
// fixed-shift softmax (R10, measured win). UNCHANGED from R10.
// ===========================================================================
#define QSTR 136   // fp16 elems per smem row (128 + 8 pad), 272B stride
#define KS_ELEMS (128 * QSTR)
#define STG_ELEMS (64 * QSTR)
// layout: Ks | Q0 | V0 | Q1 | V1
#define ATTN_SMEM ((KS_ELEMS + 4 * STG_ELEMS) * (int)sizeof(__half))  // 104448 B

__global__ __launch_bounds__(256, 2) void attn_mma_kernel(
    const __half* __restrict__ qkv, __half* __restrict__ O)
{
    const int h  = blockIdx.y;
    const int b  = blockIdx.z;
    const int i0 = blockIdx.x * 128;

    const size_t head_stride = (size_t)Ll * HDh;
    const __half* qb = qkv + ((size_t)b * 3 * NHh + 0 * NHh + h) * head_stride;
    const __half* kb = qkv + ((size_t)b * 3 * NHh + 1 * NHh + h) * head_stride;
    const __half* vb = qkv + ((size_t)b * 3 * NHh + 2 * NHh + h) * head_stride;

    extern __shared__ __half smh[];
    const uint32_t sKs = smem_u32(smh);
    const uint32_t sQ0 = sKs + KS_ELEMS * 2;          // byte addrs
    const uint32_t sV0 = sQ0 + STG_ELEMS * 2;
    const uint32_t sQ1 = sV0 + STG_ELEMS * 2;
    const uint32_t sV1 = sQ1 + STG_ELEMS * 2;

    const int tid  = threadIdx.x;
    const int lane = tid & 31;
    const int w    = tid >> 5;

    // ---- async load K tile (2048 16B chunks) ----
#pragma unroll
    for (int l = 0; l < 8; l++) {
        int idx = tid + l * 256;
        int r = idx >> 4, c = idx & 15;
        cp_async16(sKs + (uint32_t)(r * 272 + c * 16),
                   kb + (size_t)(i0 + r) * HDh + c * 8);
    }
    // ---- async load Q/V stage ----
    auto ldg_qv_async = [&](int jt, uint32_t qdst, uint32_t vdst) {
        int j0 = jt * 64;
#pragma unroll
        for (int l = 0; l < 4; l++) {
            int idx = tid + l * 256;
            int r = idx >> 4, c = idx & 15;
            uint32_t off = (uint32_t)(r * 272 + c * 16);
            cp_async16(qdst + off, qb + (size_t)(j0 + r) * HDh + c * 8);
            cp_async16(vdst + off, vb + (size_t)(j0 + r) * HDh + c * 8);
        }
    };
    ldg_qv_async(0, sQ0, sV0);
    cp_commit();                      // group 0: K + Q0 + V0

    float l0 = 0.f, l1 = 0.f;         // thread-local partial row sums
    float of[16][4];
#pragma unroll
    for (int f = 0; f < 16; f++)
#pragma unroll
        for (int c = 0; c < 4; c++) of[f][c] = 0.f;

    // exp(s/sqrt(d)) = exp2(s * rscale * log2e)
    const float cexp = 0.12753785f;   // 0.088388348 * 1.44269504
    const int a_row = lane & 15;
    const int a_col = (lane >> 4) << 3;

    const int NT = Ll / 64;
    for (int jt = 0; jt < NT; jt++) {
        if (jt + 1 < NT) {
            ldg_qv_async(jt + 1, ((jt + 1) & 1) ? sQ1 : sQ0,
                                 ((jt + 1) & 1) ? sV1 : sV0);
            cp_commit();
            cp_wait<1>();             // retire group jt
        } else {
            cp_wait<0>();
        }
        __syncthreads();              // stage jt visible to all warps

        const uint32_t sQ = (jt & 1) ? sQ1 : sQ0;
        const uint32_t sV = (jt & 1) ? sV1 : sV0;

        // ---- S = K_i · Q_j : m16 x n64, k=128 ----
        float sf[8][4];
#pragma unroll
        for (int nf = 0; nf < 8; nf++)
#pragma unroll
            for (int c = 0; c < 4; c++) sf[nf][c] = 0.f;

#pragma unroll
        for (int kk = 0; kk < 8; kk++) {
            int k16b = kk * 32;       // byte offset
            uint32_t af[4];
            ldsm_x4(af[0], af[1], af[2], af[3],
                    sKs + (uint32_t)((w * 16 + a_row) * 272 + k16b + a_col * 2));
#pragma unroll
            for (int q = 0; q < 4; q++) {
                uint32_t t0, t1, t2, t3;
                ldsm_x4(t0, t1, t2, t3,
                        sQ + (uint32_t)((q * 16 + a_row) * 272 + k16b + a_col * 2));
                mma_fp16(sf[2 * q],     af, t0, t2);
                mma_fp16(sf[2 * q + 1], af, t1, t3);
            }
        }

        // ---- fixed-shift softmax numerator: p = exp2(s*cexp); local sums ----
        float rs0 = 0.f, rs1 = 0.f;
#pragma unroll
        for (int nf = 0; nf < 8; nf++) {
            sf[nf][0] = exp2f(sf[nf][0] * cexp);
            sf[nf][1] = exp2f(sf[nf][1] * cexp);
            sf[nf][2] = exp2f(sf[nf][2] * cexp);
            sf[nf][3] = exp2f(sf[nf][3] * cexp);
            rs0 += sf[nf][0] + sf[nf][1];
            rs1 += sf[nf][2] + sf[nf][3];
        }
        l0 += rs0;
        l1 += rs1;

        // ---- pack P fragments (register-only) ----
        uint32_t pf[4][4];
#pragma unroll
        for (int kc = 0; kc < 4; kc++) {
            __half2 hh;
            hh = __floats2half2_rn(sf[2 * kc][0], sf[2 * kc][1]);         pf[kc][0] = *(uint32_t*)&hh;
            hh = __floats2half2_rn(sf[2 * kc][2], sf[2 * kc][3]);         pf[kc][1] = *(uint32_t*)&hh;
            hh = __floats2half2_rn(sf[2 * kc + 1][0], sf[2 * kc + 1][1]); pf[kc][2] = *(uint32_t*)&hh;
            hh = __floats2half2_rn(sf[2 * kc + 1][2], sf[2 * kc + 1][3]); pf[kc][3] = *(uint32_t*)&hh;
        }

        // ---- O += P @ V : m16 x n128, k=64 ----
#pragma unroll
        for (int kc = 0; kc < 4; kc++) {
#pragma unroll
            for (int nb = 0; nb < 8; nb++) {
                uint32_t t0, t1, t2, t3;
                ldsm_x4_t(t0, t1, t2, t3,
                          sV + (uint32_t)((kc * 16 + a_row) * 272 + nb * 32 + a_col * 2));
                mma_fp16(of[2 * nb],     pf[kc], t0, t1);
                mma_fp16(of[2 * nb + 1], pf[kc], t2, t3);
            }
        }

        __syncthreads();   // stage jt fully consumed before jt+1 overwrites (2-stage)
    }

    // ---- one row-sum reduce at the end (quad lanes) ----
    l0 += __shfl_xor_sync(0xffffffffu, l0, 1);
    l0 += __shfl_xor_sync(0xffffffffu, l0, 2);
    l1 += __shfl_xor_sync(0xffffffffu, l1, 1);
    l1 += __shfl_xor_sync(0xffffffffu, l1, 2);

    // ---- write O as fp16 (input of proj GEMM) ----
    float inv0 = 1.f / l0, inv1 = 1.f / l1;
    int row_g = i0 + w * 16 + (lane >> 2);
    __half* base = O + ((size_t)b * Ll + row_g) * Dd + h * HDh + (lane & 3) * 2;
#pragma unroll
    for (int nf = 0; nf < 16; nf++) {
        __half2 p0 = __floats2half2_rn(of[nf][0] * inv0, of[nf][1] * inv0);
        __half2 p1 = __floats2half2_rn(of[nf][2] * inv1, of[nf][3] * inv1);
        *(__half2*)(base + nf * 8)          = p0;
        *(__half2*)(base + 8 * Dd + nf * 8) = p1;
    }
}

// ---------------------------------------------------------------------------
extern "C" void kernel_launch(void* const* d_in, const int* in_sizes, int n_in,
                              void* d_out, int out_size)
{
    const float* x     = (const float*)d_in[0];
    const float* w_qkv = (const float*)d_in[1];
    const float* b_qkv = (const float*)d_in[2];
    const float* w_out = (const float*)d_in[3];
    const float* b_out = (const float*)d_in[4];
    float* out = (float*)d_out;

    __half *qkvh, *xh, *wqt, *wot, *oh;
    cudaGetSymbolAddress((void**)&qkvh, g_qkvh);
    cudaGetSymbolAddress((void**)&xh,   g_xh);
    cudaGetSymbolAddress((void**)&wqt,  g_wqt);
    cudaGetSymbolAddress((void**)&wot,  g_wot);
    cudaGetSymbolAddress((void**)&oh,   g_oh);

    cudaFuncSetAttribute(gemm_fp16_kernel<true>,
                         cudaFuncAttributeMaxDynamicSharedMemorySize, GEMM_SMEM);
    cudaFuncSetAttribute(gemm_fp16_kernel<false>,
                         cudaFuncAttributeMaxDynamicSharedMemorySize, GEMM_SMEM);
    cudaFuncSetAttribute(attn_mma_kernel,
                         cudaFuncAttributeMaxDynamicSharedMemorySize, ATTN_SMEM);

    // 0) fused prep: convert x + transpose/convert both weights (one launch)
    prep_kernel<<<PREP_GRID, 256>>>(x, xh, w_qkv, wqt, w_out, wot);

    // 1) QKV = X @ W_qkv + b_qkv  -> fp16
    gemm_fp16_kernel<true><<<dim3(3 * Dd / GBN, Mtot / GBM), 256, GEMM_SMEM>>>(
        xh, wqt, b_qkv, qkvh, 3 * Dd, Dd);

    // 2) attention (flash, fp16 mma, fixed-shift softmax) -> fp16 O
    attn_mma_kernel<<<dim3(Ll / 128, NHh, Bb), 256, ATTN_SMEM>>>(qkvh, oh);

    // 3) out = O @ W_out + b_out  -> fp32
    gemm_fp16_kernel<false><<<dim3(Dd / GBN, Mtot / GBM), 256, GEMM_SMEM>>>(
        oh, wot, b_out, out, Dd, Dd);
}

// round 13
// speedup vs baseline: 1.0819x; 1.0819x over previous
#include <cuda_runtime.h>
#include <cuda_fp16.h>
#include <cstdint>

// Problem constants
#define Bb  2
#define Ll  2048
#define Dd  2048
#define NHh 16
#define HDh 128
#define Mtot (Bb * Ll)   // 4096

// Scratch (static device globals: allocation-free per harness rules)
__device__ __half g_qkvh[(size_t)Mtot * 3 * Dd];   // 50 MB (fp16 QKV)
__device__ __half g_xh  [(size_t)Mtot * Dd];       // 16 MB
__device__ __half g_wqt [(size_t)3 * Dd * Dd];     // 24 MB (W_qkv^T, K-major)
__device__ __half g_wot [(size_t)Dd * Dd];         //  8 MB (W_out^T, K-major)
__device__ __half g_oh  [(size_t)Mtot * Dd];       // 16 MB (attention O)

// ===========================================================================
// helpers
// ===========================================================================
__device__ __forceinline__ uint32_t smem_u32(const void* p) {
    return (uint32_t)__cvta_generic_to_shared(p);
}
__device__ __forceinline__ void ldsm_x4(uint32_t& r0, uint32_t& r1,
                                        uint32_t& r2, uint32_t& r3, uint32_t addr) {
    asm volatile("ldmatrix.sync.aligned.m8n8.x4.shared.b16 {%0,%1,%2,%3}, [%4];"
                 : "=r"(r0), "=r"(r1), "=r"(r2), "=r"(r3) : "r"(addr));
}
__device__ __forceinline__ void ldsm_x4_t(uint32_t& r0, uint32_t& r1,
                                          uint32_t& r2, uint32_t& r3, uint32_t addr) {
    asm volatile("ldmatrix.sync.aligned.m8n8.x4.trans.shared.b16 {%0,%1,%2,%3}, [%4];"
                 : "=r"(r0), "=r"(r1), "=r"(r2), "=r"(r3) : "r"(addr));
}
__device__ __forceinline__ void mma_fp16(float (&d)[4], const uint32_t (&a)[4],
                                         const uint32_t b0, const uint32_t b1) {
    asm volatile(
        "mma.sync.aligned.m16n8k16.row.col.f32.f16.f16.f32 "
        "{%0,%1,%2,%3},{%4,%5,%6,%7},{%8,%9},{%0,%1,%2,%3};"
        : "+f"(d[0]), "+f"(d[1]), "+f"(d[2]), "+f"(d[3])
        : "r"(a[0]), "r"(a[1]), "r"(a[2]), "r"(a[3]), "r"(b0), "r"(b1));
}
__device__ __forceinline__ void cp_async16(uint32_t d, const void* g) {
    asm volatile("cp.async.cg.shared.global [%0], [%1], 16;" :: "r"(d), "l"(g) : "memory");
}
__device__ __forceinline__ void cp_commit() {
    asm volatile("cp.async.commit_group;" ::: "memory");
}
template<int n> __device__ __forceinline__ void cp_wait() {
    asm volatile("cp.async.wait_group %0;" :: "n"(n) : "memory");
}
__device__ __forceinline__ uint32_t sw128(uint32_t bo) {   // Swizzle<3,4,3>
    return bo ^ ((bo >> 3) & 0x70);
}

// ===========================================================================
// fused prep kernel: x fp32->fp16 convert + both weight transpose/converts
// (kept from R11 — measured ~10us savings vs three launches)
// ===========================================================================
#define PREP_X_BLKS  8192
#define PREP_WQ_BLKS 12288
#define PREP_GRID    24576

__global__ __launch_bounds__(256) void prep_kernel(
    const float* __restrict__ X,  __half* __restrict__ Xh,
    const float* __restrict__ Wq, __half* __restrict__ Wqt,
    const float* __restrict__ Wo, __half* __restrict__ Wot)
{
    __shared__ float t[32][33];
    const int bid = blockIdx.x;
    if (bid < PREP_X_BLKS) {
        size_t i = (size_t)bid * 256 + threadIdx.x;   // float4 index
        float4 v = ((const float4*)X)[i];
        __half2 a = __floats2half2_rn(v.x, v.y);
        __half2 b = __floats2half2_rn(v.z, v.w);
        ((uint2*)Xh)[i] = make_uint2(*(uint32_t*)&a, *(uint32_t*)&b);
        return;
    }
    // transpose job: W [K][N] fp32 -> T [N][K] fp16
    const float* W; __half* T; int N, tile;
    if (bid < PREP_X_BLKS + PREP_WQ_BLKS) {
        W = Wq; T = Wqt; N = 3 * Dd; tile = bid - PREP_X_BLKS;
    } else {
        W = Wo; T = Wot; N = Dd;     tile = bid - PREP_X_BLKS - PREP_WQ_BLKS;
    }
    const int ntiles_n = N / 32;
    const int n0 = (tile % ntiles_n) * 32;
    const int k0 = (tile / ntiles_n) * 32;
    const int c = threadIdx.x & 31, r8 = threadIdx.x >> 5;
#pragma unroll
    for (int i = 0; i < 4; i++) {
        int r = r8 + i * 8;
        t[r][c] = W[(size_t)(k0 + r) * N + n0 + c];
    }
    __syncthreads();
#pragma unroll
    for (int i = 0; i < 4; i++) {
        int r = r8 + i * 8;                      // local n index
        T[(size_t)(n0 + r) * Dd + k0 + c] = __float2half_rn(t[c][r]);  // K = Dd always
    }
}

// ===========================================================================
// fp16 GEMM (mma.sync): C[M,N] = A[M,K] @ B[N,K]^T + bias
// BM=128, BN=128, BK=64. 256 threads = 8 warps (4m x 2n), warp tile 32x64.
// FROZEN R9 mainloop: 3-stage ring, distance-2 prefetch, loads issued
// BEFORE the wait, two barriers per chunk. Measured 307.8us (QKV) /
// tensor=64.3%. Both attempted "improvements" (R8 distance-1, R11 reorder)
// regressed — do not touch.
// ===========================================================================
#define GBM 128
#define GBN 128
#define GBK 64
#define GA_BYTES (GBM * 128)               // 16384
#define GB_BYTES (GBN * 128)               // 16384
#define GSTAGE_B (GA_BYTES + GB_BYTES)     // 32768
#define GNST 3
#define GEMM_SMEM (GNST * GSTAGE_B)        // 98304

template<bool OUT_HALF>
__global__ __launch_bounds__(256, 2) void gemm_fp16_kernel(
    const __half* __restrict__ A, const __half* __restrict__ Bw,
    const float* __restrict__ bias, void* __restrict__ Cout, int N, int K)
{
    extern __shared__ __align__(1024) uint8_t smem[];
    const uint32_t sb = smem_u32(smem);
    const int tid = threadIdx.x, lane = tid & 31, warp = tid >> 5;
    const int wm = warp >> 1, wn = warp & 1;
    const int row0 = blockIdx.y * GBM, col0 = blockIdx.x * GBN;

    float acc[2][8][4];
#pragma unroll
    for (int mi = 0; mi < 2; mi++)
#pragma unroll
        for (int ni = 0; ni < 8; ni++)
#pragma unroll
            for (int c = 0; c < 4; c++) acc[mi][ni][c] = 0.f;

    auto load_stage = [&](int s, int kc) {
        const uint32_t st = sb + s * GSTAGE_B;
        const int k0 = kc * GBK;
#pragma unroll
        for (int i = 0; i < 4; i++) {          // A: 1024 16B chunks
            int idx = tid + i * 256;
            int r = idx >> 3, c = idx & 7;
            uint32_t bo = (uint32_t)(r * 128 + c * 16);
            cp_async16(st + sw128(bo), A + (size_t)(row0 + r) * K + k0 + c * 8);
        }
#pragma unroll
        for (int i = 0; i < 4; i++) {          // B: 1024 16B chunks
            int idx = tid + i * 256;
            int r = idx >> 3, c = idx & 7;
            uint32_t bo = (uint32_t)(r * 128 + c * 16);
            cp_async16(st + GA_BYTES + sw128(bo),
                       Bw + (size_t)(col0 + r) * K + k0 + c * 8);
        }
    };

    const int lrow = lane & 15;
    const int lcol = (lane >> 4) * 16;         // byte offset of k-chunk

    auto compute = [&](int s) {
        const uint32_t stA = sb + s * GSTAGE_B;
        const uint32_t stB = stA + GA_BYTES;
#pragma unroll
        for (int k16 = 0; k16 < 4; k16++) {
            uint32_t a[2][4];
#pragma unroll
            for (int mi = 0; mi < 2; mi++) {
                uint32_t bo = (uint32_t)((wm * 32 + mi * 16 + lrow) * 128 + k16 * 32 + lcol);
                ldsm_x4(a[mi][0], a[mi][1], a[mi][2], a[mi][3], stA + sw128(bo));
            }
            uint32_t bf[8][2];
#pragma unroll
            for (int nb = 0; nb < 4; nb++) {
                uint32_t bo = (uint32_t)((wn * 64 + nb * 16 + lrow) * 128 + k16 * 32 + lcol);
                uint32_t t0, t1, t2, t3;
                ldsm_x4(t0, t1, t2, t3, stB + sw128(bo));
                bf[2 * nb][0] = t0; bf[2 * nb][1] = t2;      // n8 lo: k0-7,k8-15
                bf[2 * nb + 1][0] = t1; bf[2 * nb + 1][1] = t3;
            }
#pragma unroll
            for (int mi = 0; mi < 2; mi++)
#pragma unroll
                for (int ni = 0; ni < 8; ni++)
                    mma_fp16(acc[mi][ni], a[mi], bf[ni][0], bf[ni][1]);
        }
    };

    const int nKC = K / GBK;                   // 32
    load_stage(0, 0); cp_commit();
    load_stage(1, 1); cp_commit();

    for (int kc = 0; kc < nKC; kc++) {
        const int s = kc % GNST;
        if (kc + 2 < nKC) { load_stage((kc + 2) % GNST, kc + 2); cp_commit(); }
        const int later = (nKC - 1 - kc) < 2 ? (nKC - 1 - kc) : 2;
        if (later == 2)      cp_wait<2>();
        else if (later == 1) cp_wait<1>();
        else                 cp_wait<0>();
        __syncthreads();
        compute(s);
        __syncthreads();
    }

    // Epilogue
    const int g  = lane >> 2;
    const int i2 = (lane & 3) * 2;
#pragma unroll
    for (int mi = 0; mi < 2; mi++) {
#pragma unroll
        for (int ni = 0; ni < 8; ni++) {
            int col = col0 + wn * 64 + ni * 8 + i2;
            float bx = bias[col], by = bias[col + 1];
            int r_top = row0 + wm * 32 + mi * 16 + g;
            float v0 = acc[mi][ni][0] + bx, v1 = acc[mi][ni][1] + by;
            float v2 = acc[mi][ni][2] + bx, v3 = acc[mi][ni][3] + by;
            if (OUT_HALF) {
                __half* C = (__half*)Cout;
                __half2 p0 = __floats2half2_rn(v0, v1);
                __half2 p1 = __floats2half2_rn(v2, v3);
                *(__half2*)(C + (size_t)r_top * N + col)       = p0;
                *(__half2*)(C + (size_t)(r_top + 8) * N + col) = p1;
            } else {
                float* C = (float*)Cout;
                *(float2*)(C + (size_t)r_top * N + col)       = make_float2(v0, v1);
                *(float2*)(C + (size_t)(r_top + 8) * N + col) = make_float2(v2, v3);
            }
        }
    }
}

// ===========================================================================
// Flash attention, fp16 MMA. cp.async Q/V double buffer, 2 CTAs/SM,
// fixed-shift softmax. UNCHANGED from R10 (measured ~229us).
// ===========================================================================
#define QSTR 136   // fp16 elems per smem row (128 + 8 pad), 272B stride
#define KS_ELEMS (128 * QSTR)
#define STG_ELEMS (64 * QSTR)
// layout: Ks | Q0 | V0 | Q1 | V1
#define ATTN_SMEM ((KS_ELEMS + 4 * STG_ELEMS) * (int)sizeof(__half))  // 104448 B

__global__ __launch_bounds__(256, 2) void attn_mma_kernel(
    const __half* __restrict__ qkv, __half* __restrict__ O)
{
    const int h  = blockIdx.y;
    const int b  = blockIdx.z;
    const int i0 = blockIdx.x * 128;

    const size_t head_stride = (size_t)Ll * HDh;
    const __half* qb = qkv + ((size_t)b * 3 * NHh + 0 * NHh + h) * head_stride;
    const __half* kb = qkv + ((size_t)b * 3 * NHh + 1 * NHh + h) * head_stride;
    const __half* vb = qkv + ((size_t)b * 3 * NHh + 2 * NHh + h) * head_stride;

    extern __shared__ __half smh[];
    const uint32_t sKs = smem_u32(smh);
    const uint32_t sQ0 = sKs + KS_ELEMS * 2;          // byte addrs
    const uint32_t sV0 = sQ0 + STG_ELEMS * 2;
    const uint32_t sQ1 = sV0 + STG_ELEMS * 2;
    const uint32_t sV1 = sQ1 + STG_ELEMS * 2;

    const int tid  = threadIdx.x;
    const int lane = tid & 31;
    const int w    = tid >> 5;

    // ---- async load K tile (2048 16B chunks) ----
#pragma unroll
    for (int l = 0; l < 8; l++) {
        int idx = tid + l * 256;
        int r = idx >> 4, c = idx & 15;
        cp_async16(sKs + (uint32_t)(r * 272 + c * 16),
                   kb + (size_t)(i0 + r) * HDh + c * 8);
    }
    // ---- async load Q/V stage ----
    auto ldg_qv_async = [&](int jt, uint32_t qdst, uint32_t vdst) {
        int j0 = jt * 64;
#pragma unroll
        for (int l = 0; l < 4; l++) {
            int idx = tid + l * 256;
            int r = idx >> 4, c = idx & 15;
            uint32_t off = (uint32_t)(r * 272 + c * 16);
            cp_async16(qdst + off, qb + (size_t)(j0 + r) * HDh + c * 8);
            cp_async16(vdst + off, vb + (size_t)(j0 + r) * HDh + c * 8);
        }
    };
    ldg_qv_async(0, sQ0, sV0);
    cp_commit();                      // group 0: K + Q0 + V0

    float l0 = 0.f, l1 = 0.f;         // thread-local partial row sums
    float of[16][4];
#pragma unroll
    for (int f = 0; f < 16; f++)
#pragma unroll
        for (int c = 0; c < 4; c++) of[f][c] = 0.f;

    // exp(s/sqrt(d)) = exp2(s * rscale * log2e)
    const float cexp = 0.12753785f;   // 0.088388348 * 1.44269504
    const int a_row = lane & 15;
    const int a_col = (lane >> 4) << 3;

    const int NT = Ll / 64;
    for (int jt = 0; jt < NT; jt++) {
        if (jt + 1 < NT) {
            ldg_qv_async(jt + 1, ((jt + 1) & 1) ? sQ1 : sQ0,
                                 ((jt + 1) & 1) ? sV1 : sV0);
            cp_commit();
            cp_wait<1>();             // retire group jt
        } else {
            cp_wait<0>();
        }
        __syncthreads();              // stage jt visible to all warps

        const uint32_t sQ = (jt & 1) ? sQ1 : sQ0;
        const uint32_t sV = (jt & 1) ? sV1 : sV0;

        // ---- S = K_i · Q_j : m16 x n64, k=128 ----
        float sf[8][4];
#pragma unroll
        for (int nf = 0; nf < 8; nf++)
#pragma unroll
            for (int c = 0; c < 4; c++) sf[nf][c] = 0.f;

#pragma unroll
        for (int kk = 0; kk < 8; kk++) {
            int k16b = kk * 32;       // byte offset
            uint32_t af[4];
            ldsm_x4(af[0], af[1], af[2], af[3],
                    sKs + (uint32_t)((w * 16 + a_row) * 272 + k16b + a_col * 2));
#pragma unroll
            for (int q = 0; q < 4; q++) {
                uint32_t t0, t1, t2, t3;
                ldsm_x4(t0, t1, t2, t3,
                        sQ + (uint32_t)((q * 16 + a_row) * 272 + k16b + a_col * 2));
                mma_fp16(sf[2 * q],     af, t0, t2);
                mma_fp16(sf[2 * q + 1], af, t1, t3);
            }
        }

        // ---- fixed-shift softmax numerator: p = exp2(s*cexp); local sums ----
        float rs0 = 0.f, rs1 = 0.f;
#pragma unroll
        for (int nf = 0; nf < 8; nf++) {
            sf[nf][0] = exp2f(sf[nf][0] * cexp);
            sf[nf][1] = exp2f(sf[nf][1] * cexp);
            sf[nf][2] = exp2f(sf[nf][2] * cexp);
            sf[nf][3] = exp2f(sf[nf][3] * cexp);
            rs0 += sf[nf][0] + sf[nf][1];
            rs1 += sf[nf][2] + sf[nf][3];
        }
        l0 += rs0;
        l1 += rs1;

        // ---- pack P fragments (register-only) ----
        uint32_t pf[4][4];
#pragma unroll
        for (int kc = 0; kc < 4; kc++) {
            __half2 hh;
            hh = __floats2half2_rn(sf[2 * kc][0], sf[2 * kc][1]);         pf[kc][0] = *(uint32_t*)&hh;
            hh = __floats2half2_rn(sf[2 * kc][2], sf[2 * kc][3]);         pf[kc][1] = *(uint32_t*)&hh;
            hh = __floats2half2_rn(sf[2 * kc + 1][0], sf[2 * kc + 1][1]); pf[kc][2] = *(uint32_t*)&hh;
            hh = __floats2half2_rn(sf[2 * kc + 1][2], sf[2 * kc + 1][3]); pf[kc][3] = *(uint32_t*)&hh;
        }

        // ---- O += P @ V : m16 x n128, k=64 ----
#pragma unroll
        for (int kc = 0; kc < 4; kc++) {
#pragma unroll
            for (int nb = 0; nb < 8; nb++) {
                uint32_t t0, t1, t2, t3;
                ldsm_x4_t(t0, t1, t2, t3,
                          sV + (uint32_t)((kc * 16 + a_row) * 272 + nb * 32 + a_col * 2));
                mma_fp16(of[2 * nb],     pf[kc], t0, t1);
                mma_fp16(of[2 * nb + 1], pf[kc], t2, t3);
            }
        }

        __syncthreads();   // stage jt fully consumed before jt+1 overwrites (2-stage)
    }

    // ---- one row-sum reduce at the end (quad lanes) ----
    l0 += __shfl_xor_sync(0xffffffffu, l0, 1);
    l0 += __shfl_xor_sync(0xffffffffu, l0, 2);
    l1 += __shfl_xor_sync(0xffffffffu, l1, 1);
    l1 += __shfl_xor_sync(0xffffffffu, l1, 2);

    // ---- write O as fp16 (input of proj GEMM) ----
    float inv0 = 1.f / l0, inv1 = 1.f / l1;
    int row_g = i0 + w * 16 + (lane >> 2);
    __half* base = O + ((size_t)b * Ll + row_g) * Dd + h * HDh + (lane & 3) * 2;
#pragma unroll
    for (int nf = 0; nf < 16; nf++) {
        __half2 p0 = __floats2half2_rn(of[nf][0] * inv0, of[nf][1] * inv0);
        __half2 p1 = __floats2half2_rn(of[nf][2] * inv1, of[nf][3] * inv1);
        *(__half2*)(base + nf * 8)          = p0;
        *(__half2*)(base + 8 * Dd + nf * 8) = p1;
    }
}

// ---------------------------------------------------------------------------
extern "C" void kernel_launch(void* const* d_in, const int* in_sizes, int n_in,
                              void* d_out, int out_size)
{
    const float* x     = (const float*)d_in[0];
    const float* w_qkv = (const float*)d_in[1];
    const float* b_qkv = (const float*)d_in[2];
    const float* w_out = (const float*)d_in[3];
    const float* b_out = (const float*)d_in[4];
    float* out = (float*)d_out;

    __half *qkvh, *xh, *wqt, *wot, *oh;
    cudaGetSymbolAddress((void**)&qkvh, g_qkvh);
    cudaGetSymbolAddress((void**)&xh,   g_xh);
    cudaGetSymbolAddress((void**)&wqt,  g_wqt);
    cudaGetSymbolAddress((void**)&wot,  g_wot);
    cudaGetSymbolAddress((void**)&oh,   g_oh);

    cudaFuncSetAttribute(gemm_fp16_kernel<true>,
                         cudaFuncAttributeMaxDynamicSharedMemorySize, GEMM_SMEM);
    cudaFuncSetAttribute(gemm_fp16_kernel<false>,
                         cudaFuncAttributeMaxDynamicSharedMemorySize, GEMM_SMEM);
    cudaFuncSetAttribute(attn_mma_kernel,
                         cudaFuncAttributeMaxDynamicSharedMemorySize, ATTN_SMEM);

    // 0) fused prep: convert x + transpose/convert both weights (one launch)
    prep_kernel<<<PREP_GRID, 256>>>(x, xh, w_qkv, wqt, w_out, wot);

    // 1) QKV = X @ W_qkv + b_qkv  -> fp16
    gemm_fp16_kernel<true><<<dim3(3 * Dd / GBN, Mtot / GBM), 256, GEMM_SMEM>>>(
        xh, wqt, b_qkv, qkvh, 3 * Dd, Dd);

    // 2) attention (flash, fp16 mma, fixed-shift softmax) -> fp16 O
    attn_mma_kernel<<<dim3(Ll / 128, NHh, Bb), 256, ATTN_SMEM>>>(qkvh, oh);

    // 3) out = O @ W_out + b_out  -> fp32
    gemm_fp16_kernel<false><<<dim3(Dd / GBN, Mtot / GBM), 256, GEMM_SMEM>>>(
        oh, wot, b_out, out, Dd, Dd);
}

// round 15
// speedup vs baseline: 1.1152x; 1.0307x over previous
#include <cuda_runtime.h>
#include <cuda_fp16.h>
#include <cstdint>

// Problem constants
#define Bb  2
#define Ll  2048
#define Dd  2048
#define NHh 16
#define HDh 128
#define Mtot (Bb * Ll)   // 4096

// Scratch (static device globals: allocation-free per harness rules)
__device__ __half g_qkvh[(size_t)Mtot * 3 * Dd];   // 50 MB (fp16 QKV)
__device__ __half g_xh  [(size_t)Mtot * Dd];       // 16 MB
__device__ __half g_wqt [(size_t)3 * Dd * Dd];     // 24 MB (W_qkv^T, K-major)
__device__ __half g_wot [(size_t)Dd * Dd];         //  8 MB (W_out^T, K-major)
__device__ __half g_oh  [(size_t)Mtot * Dd];       // 16 MB (attention O)

// ===========================================================================
// helpers
// ===========================================================================
__device__ __forceinline__ uint32_t smem_u32(const void* p) {
    return (uint32_t)__cvta_generic_to_shared(p);
}
__device__ __forceinline__ void ldsm_x4(uint32_t& r0, uint32_t& r1,
                                        uint32_t& r2, uint32_t& r3, uint32_t addr) {
    asm volatile("ldmatrix.sync.aligned.m8n8.x4.shared.b16 {%0,%1,%2,%3}, [%4];"
                 : "=r"(r0), "=r"(r1), "=r"(r2), "=r"(r3) : "r"(addr));
}
__device__ __forceinline__ void ldsm_x4_t(uint32_t& r0, uint32_t& r1,
                                          uint32_t& r2, uint32_t& r3, uint32_t addr) {
    asm volatile("ldmatrix.sync.aligned.m8n8.x4.trans.shared.b16 {%0,%1,%2,%3}, [%4];"
                 : "=r"(r0), "=r"(r1), "=r"(r2), "=r"(r3) : "r"(addr));
}
__device__ __forceinline__ void mma_fp16(float (&d)[4], const uint32_t (&a)[4],
                                         const uint32_t b0, const uint32_t b1) {
    asm volatile(
        "mma.sync.aligned.m16n8k16.row.col.f32.f16.f16.f32 "
        "{%0,%1,%2,%3},{%4,%5,%6,%7},{%8,%9},{%0,%1,%2,%3};"
        : "+f"(d[0]), "+f"(d[1]), "+f"(d[2]), "+f"(d[3])
        : "r"(a[0]), "r"(a[1]), "r"(a[2]), "r"(a[3]), "r"(b0), "r"(b1));
}
__device__ __forceinline__ void cp_async16(uint32_t d, const void* g) {
    asm volatile("cp.async.cg.shared.global [%0], [%1], 16;" :: "r"(d), "l"(g) : "memory");
}
__device__ __forceinline__ void cp_commit() {
    asm volatile("cp.async.commit_group;" ::: "memory");
}
template<int n> __device__ __forceinline__ void cp_wait() {
    asm volatile("cp.async.wait_group %0;" :: "n"(n) : "memory");
}
__device__ __forceinline__ uint32_t sw128(uint32_t bo) {   // Swizzle<3,4,3>
    return bo ^ ((bo >> 3) & 0x70);
}

// ===========================================================================
// fused prep kernel (frozen from R11/R12)
// ===========================================================================
#define PREP_X_BLKS  8192
#define PREP_WQ_BLKS 12288
#define PREP_GRID    24576

__global__ __launch_bounds__(256) void prep_kernel(
    const float* __restrict__ X,  __half* __restrict__ Xh,
    const float* __restrict__ Wq, __half* __restrict__ Wqt,
    const float* __restrict__ Wo, __half* __restrict__ Wot)
{
    __shared__ float t[32][33];
    const int bid = blockIdx.x;
    if (bid < PREP_X_BLKS) {
        size_t i = (size_t)bid * 256 + threadIdx.x;   // float4 index
        float4 v = ((const float4*)X)[i];
        __half2 a = __floats2half2_rn(v.x, v.y);
        __half2 b = __floats2half2_rn(v.z, v.w);
        ((uint2*)Xh)[i] = make_uint2(*(uint32_t*)&a, *(uint32_t*)&b);
        return;
    }
    const float* W; __half* T; int N, tile;
    if (bid < PREP_X_BLKS + PREP_WQ_BLKS) {
        W = Wq; T = Wqt; N = 3 * Dd; tile = bid - PREP_X_BLKS;
    } else {
        W = Wo; T = Wot; N = Dd;     tile = bid - PREP_X_BLKS - PREP_WQ_BLKS;
    }
    const int ntiles_n = N / 32;
    const int n0 = (tile % ntiles_n) * 32;
    const int k0 = (tile / ntiles_n) * 32;
    const int c = threadIdx.x & 31, r8 = threadIdx.x >> 5;
#pragma unroll
    for (int i = 0; i < 4; i++) {
        int r = r8 + i * 8;
        t[r][c] = W[(size_t)(k0 + r) * N + n0 + c];
    }
    __syncthreads();
#pragma unroll
    for (int i = 0; i < 4; i++) {
        int r = r8 + i * 8;
        T[(size_t)(n0 + r) * Dd + k0 + c] = __float2half_rn(t[c][r]);
    }
}

// ===========================================================================
// fp16 GEMM — FROZEN R9 mainloop (measured 307.8us QKV / tensor 64.3%).
// ===========================================================================
#define GBM 128
#define GBN 128
#define GBK 64
#define GA_BYTES (GBM * 128)               // 16384
#define GB_BYTES (GBN * 128)               // 16384
#define GSTAGE_B (GA_BYTES + GB_BYTES)     // 32768
#define GNST 3
#define GEMM_SMEM (GNST * GSTAGE_B)        // 98304

template<bool OUT_HALF>
__global__ __launch_bounds__(256, 2) void gemm_fp16_kernel(
    const __half* __restrict__ A, const __half* __restrict__ Bw,
    const float* __restrict__ bias, void* __restrict__ Cout, int N, int K)
{
    extern __shared__ __align__(1024) uint8_t smem[];
    const uint32_t sb = smem_u32(smem);
    const int tid = threadIdx.x, lane = tid & 31, warp = tid >> 5;
    const int wm = warp >> 1, wn = warp & 1;
    const int row0 = blockIdx.y * GBM, col0 = blockIdx.x * GBN;

    float acc[2][8][4];
#pragma unroll
    for (int mi = 0; mi < 2; mi++)
#pragma unroll
        for (int ni = 0; ni < 8; ni++)
#pragma unroll
            for (int c = 0; c < 4; c++) acc[mi][ni][c] = 0.f;

    auto load_stage = [&](int s, int kc) {
        const uint32_t st = sb + s * GSTAGE_B;
        const int k0 = kc * GBK;
#pragma unroll
        for (int i = 0; i < 4; i++) {
            int idx = tid + i * 256;
            int r = idx >> 3, c = idx & 7;
            uint32_t bo = (uint32_t)(r * 128 + c * 16);
            cp_async16(st + sw128(bo), A + (size_t)(row0 + r) * K + k0 + c * 8);
        }
#pragma unroll
        for (int i = 0; i < 4; i++) {
            int idx = tid + i * 256;
            int r = idx >> 3, c = idx & 7;
            uint32_t bo = (uint32_t)(r * 128 + c * 16);
            cp_async16(st + GA_BYTES + sw128(bo),
                       Bw + (size_t)(col0 + r) * K + k0 + c * 8);
        }
    };

    const int lrow = lane & 15;
    const int lcol = (lane >> 4) * 16;

    auto compute = [&](int s) {
        const uint32_t stA = sb + s * GSTAGE_B;
        const uint32_t stB = stA + GA_BYTES;
#pragma unroll
        for (int k16 = 0; k16 < 4; k16++) {
            uint32_t a[2][4];
#pragma unroll
            for (int mi = 0; mi < 2; mi++) {
                uint32_t bo = (uint32_t)((wm * 32 + mi * 16 + lrow) * 128 + k16 * 32 + lcol);
                ldsm_x4(a[mi][0], a[mi][1], a[mi][2], a[mi][3], stA + sw128(bo));
            }
            uint32_t bf[8][2];
#pragma unroll
            for (int nb = 0; nb < 4; nb++) {
                uint32_t bo = (uint32_t)((wn * 64 + nb * 16 + lrow) * 128 + k16 * 32 + lcol);
                uint32_t t0, t1, t2, t3;
                ldsm_x4(t0, t1, t2, t3, stB + sw128(bo));
                bf[2 * nb][0] = t0; bf[2 * nb][1] = t2;
                bf[2 * nb + 1][0] = t1; bf[2 * nb + 1][1] = t3;
            }
#pragma unroll
            for (int mi = 0; mi < 2; mi++)
#pragma unroll
                for (int ni = 0; ni < 8; ni++)
                    mma_fp16(acc[mi][ni], a[mi], bf[ni][0], bf[ni][1]);
        }
    };

    const int nKC = K / GBK;
    load_stage(0, 0); cp_commit();
    load_stage(1, 1); cp_commit();

    for (int kc = 0; kc < nKC; kc++) {
        const int s = kc % GNST;
        if (kc + 2 < nKC) { load_stage((kc + 2) % GNST, kc + 2); cp_commit(); }
        const int later = (nKC - 1 - kc) < 2 ? (nKC - 1 - kc) : 2;
        if (later == 2)      cp_wait<2>();
        else if (later == 1) cp_wait<1>();
        else                 cp_wait<0>();
        __syncthreads();
        compute(s);
        __syncthreads();
    }

    const int g  = lane >> 2;
    const int i2 = (lane & 3) * 2;
#pragma unroll
    for (int mi = 0; mi < 2; mi++) {
#pragma unroll
        for (int ni = 0; ni < 8; ni++) {
            int col = col0 + wn * 64 + ni * 8 + i2;
            float bx = bias[col], by = bias[col + 1];
            int r_top = row0 + wm * 32 + mi * 16 + g;
            float v0 = acc[mi][ni][0] + bx, v1 = acc[mi][ni][1] + by;
            float v2 = acc[mi][ni][2] + bx, v3 = acc[mi][ni][3] + by;
            if (OUT_HALF) {
                __half* C = (__half*)Cout;
                __half2 p0 = __floats2half2_rn(v0, v1);
                __half2 p1 = __floats2half2_rn(v2, v3);
                *(__half2*)(C + (size_t)r_top * N + col)       = p0;
                *(__half2*)(C + (size_t)(r_top + 8) * N + col) = p1;
            } else {
                float* C = (float*)Cout;
                *(float2*)(C + (size_t)r_top * N + col)       = make_float2(v0, v1);
                *(float2*)(C + (size_t)(r_top + 8) * N + col) = make_float2(v2, v3);
            }
        }
    }
}

// ===========================================================================
// Flash attention v2 (R13 resubmit, reg-pressure trimmed): 128 threads,
// 4 warps, 32 i-rows per warp (two m16 groups sharing every Q and V
// fragment -> 0.625 ldsm/MMA vs 1.125). Fixed-shift softmax fused with
// P-packing per group (shortens sf live range). 2 CTAs/SM.
// ===========================================================================
#define QSTR 136
#define KS_ELEMS (128 * QSTR)
#define STG_ELEMS (64 * QSTR)
#define ATTN_SMEM ((KS_ELEMS + 4 * STG_ELEMS) * (int)sizeof(__half))  // 104448 B

__global__ __launch_bounds__(128, 2) void attn_mma_kernel(
    const __half* __restrict__ qkv, __half* __restrict__ O)
{
    const int h  = blockIdx.y;
    const int b  = blockIdx.z;
    const int i0 = blockIdx.x * 128;

    const size_t head_stride = (size_t)Ll * HDh;
    const __half* qb = qkv + ((size_t)b * 3 * NHh + 0 * NHh + h) * head_stride;
    const __half* kb = qkv + ((size_t)b * 3 * NHh + 1 * NHh + h) * head_stride;
    const __half* vb = qkv + ((size_t)b * 3 * NHh + 2 * NHh + h) * head_stride;

    extern __shared__ __half smh[];
    const uint32_t sKs = smem_u32(smh);
    const uint32_t sQ0 = sKs + KS_ELEMS * 2;
    const uint32_t sV0 = sQ0 + STG_ELEMS * 2;
    const uint32_t sQ1 = sV0 + STG_ELEMS * 2;
    const uint32_t sV1 = sQ1 + STG_ELEMS * 2;

    const int tid  = threadIdx.x;
    const int lane = tid & 31;
    const int w    = tid >> 5;          // 0..3, owns rows [w*32, w*32+32)

    // ---- async load K tile: 2048 16B chunks over 128 threads ----
#pragma unroll
    for (int l = 0; l < 16; l++) {
        int idx = tid + l * 128;
        int r = idx >> 4, c = idx & 15;
        cp_async16(sKs + (uint32_t)(r * 272 + c * 16),
                   kb + (size_t)(i0 + r) * HDh + c * 8);
    }
    // ---- async load Q/V stage: 1024 chunks each over 128 threads ----
    auto ldg_qv_async = [&](int jt, uint32_t qdst, uint32_t vdst) {
        int j0 = jt * 64;
#pragma unroll
        for (int l = 0; l < 8; l++) {
            int idx = tid + l * 128;
            int r = idx >> 4, c = idx & 15;
            uint32_t off = (uint32_t)(r * 272 + c * 16);
            cp_async16(qdst + off, qb + (size_t)(j0 + r) * HDh + c * 8);
            cp_async16(vdst + off, vb + (size_t)(j0 + r) * HDh + c * 8);
        }
    };
    ldg_qv_async(0, sQ0, sV0);
    cp_commit();

    float ls00 = 0.f, ls01 = 0.f, ls10 = 0.f, ls11 = 0.f;
    float of[2][16][4];
#pragma unroll
    for (int mg = 0; mg < 2; mg++)
#pragma unroll
        for (int f = 0; f < 16; f++)
#pragma unroll
            for (int c = 0; c < 4; c++) of[mg][f][c] = 0.f;

    const float cexp = 0.12753785f;   // (1/sqrt(128)) * log2(e)
    const int a_row = lane & 15;
    const int a_col = (lane >> 4) << 3;

    const int NT = Ll / 64;
    for (int jt = 0; jt < NT; jt++) {
        if (jt + 1 < NT) {
            ldg_qv_async(jt + 1, ((jt + 1) & 1) ? sQ1 : sQ0,
                                 ((jt + 1) & 1) ? sV1 : sV0);
            cp_commit();
            cp_wait<1>();
        } else {
            cp_wait<0>();
        }
        __syncthreads();

        const uint32_t sQ = (jt & 1) ? sQ1 : sQ0;
        const uint32_t sV = (jt & 1) ? sV1 : sV0;

        // ---- S = K_i · Q_j : m32 (two m16 groups) x n64, k=128 ----
        float sf[2][8][4];
#pragma unroll
        for (int mg = 0; mg < 2; mg++)
#pragma unroll
            for (int nf = 0; nf < 8; nf++)
#pragma unroll
                for (int c = 0; c < 4; c++) sf[mg][nf][c] = 0.f;

#pragma unroll
        for (int kk = 0; kk < 8; kk++) {
            int k16b = kk * 32;
            uint32_t af0[4], af1[4];
            ldsm_x4(af0[0], af0[1], af0[2], af0[3],
                    sKs + (uint32_t)((w * 32 + a_row) * 272 + k16b + a_col * 2));
            ldsm_x4(af1[0], af1[1], af1[2], af1[3],
                    sKs + (uint32_t)((w * 32 + 16 + a_row) * 272 + k16b + a_col * 2));
#pragma unroll
            for (int q = 0; q < 4; q++) {
                uint32_t t0, t1, t2, t3;
                ldsm_x4(t0, t1, t2, t3,
                        sQ + (uint32_t)((q * 16 + a_row) * 272 + k16b + a_col * 2));
                mma_fp16(sf[0][2 * q],     af0, t0, t2);
                mma_fp16(sf[0][2 * q + 1], af0, t1, t3);
                mma_fp16(sf[1][2 * q],     af1, t0, t2);
                mma_fp16(sf[1][2 * q + 1], af1, t1, t3);
            }
        }

        // ---- fixed-shift softmax fused with P packing (per m-group) ----
        uint32_t pf[2][4][4];
#pragma unroll
        for (int mg = 0; mg < 2; mg++) {
            float rs0 = 0.f, rs1 = 0.f;
#pragma unroll
            for (int nf = 0; nf < 8; nf++) {
                sf[mg][nf][0] = exp2f(sf[mg][nf][0] * cexp);
                sf[mg][nf][1] = exp2f(sf[mg][nf][1] * cexp);
                sf[mg][nf][2] = exp2f(sf[mg][nf][2] * cexp);
                sf[mg][nf][3] = exp2f(sf[mg][nf][3] * cexp);
                rs0 += sf[mg][nf][0] + sf[mg][nf][1];
                rs1 += sf[mg][nf][2] + sf[mg][nf][3];
            }
            if (mg == 0) { ls00 += rs0; ls01 += rs1; }
            else         { ls10 += rs0; ls11 += rs1; }
#pragma unroll
            for (int kc = 0; kc < 4; kc++) {
                __half2 hh;
                hh = __floats2half2_rn(sf[mg][2 * kc][0], sf[mg][2 * kc][1]);         pf[mg][kc][0] = *(uint32_t*)&hh;
                hh = __floats2half2_rn(sf[mg][2 * kc][2], sf[mg][2 * kc][3]);         pf[mg][kc][1] = *(uint32_t*)&hh;
                hh = __floats2half2_rn(sf[mg][2 * kc + 1][0], sf[mg][2 * kc + 1][1]); pf[mg][kc][2] = *(uint32_t*)&hh;
                hh = __floats2half2_rn(sf[mg][2 * kc + 1][2], sf[mg][2 * kc + 1][3]); pf[mg][kc][3] = *(uint32_t*)&hh;
            }
        }

        // ---- O += P @ V : each V fragment feeds both m-groups ----
#pragma unroll
        for (int kc = 0; kc < 4; kc++) {
#pragma unroll
            for (int nb = 0; nb < 8; nb++) {
                uint32_t t0, t1, t2, t3;
                ldsm_x4_t(t0, t1, t2, t3,
                          sV + (uint32_t)((kc * 16 + a_row) * 272 + nb * 32 + a_col * 2));
                mma_fp16(of[0][2 * nb],     pf[0][kc], t0, t1);
                mma_fp16(of[0][2 * nb + 1], pf[0][kc], t2, t3);
                mma_fp16(of[1][2 * nb],     pf[1][kc], t0, t1);
                mma_fp16(of[1][2 * nb + 1], pf[1][kc], t2, t3);
            }
        }

        __syncthreads();
    }

    // ---- row-sum reduce (quad lanes) ----
    ls00 += __shfl_xor_sync(0xffffffffu, ls00, 1);
    ls00 += __shfl_xor_sync(0xffffffffu, ls00, 2);
    ls01 += __shfl_xor_sync(0xffffffffu, ls01, 1);
    ls01 += __shfl_xor_sync(0xffffffffu, ls01, 2);
    ls10 += __shfl_xor_sync(0xffffffffu, ls10, 1);
    ls10 += __shfl_xor_sync(0xffffffffu, ls10, 2);
    ls11 += __shfl_xor_sync(0xffffffffu, ls11, 1);
    ls11 += __shfl_xor_sync(0xffffffffu, ls11, 2);

    // ---- write O as fp16 ----
#pragma unroll
    for (int mg = 0; mg < 2; mg++) {
        float inv0 = 1.f / (mg == 0 ? ls00 : ls10);
        float inv1 = 1.f / (mg == 0 ? ls01 : ls11);
        int row_g = i0 + w * 32 + mg * 16 + (lane >> 2);
        __half* base = O + ((size_t)b * Ll + row_g) * Dd + h * HDh + (lane & 3) * 2;
#pragma unroll
        for (int nf = 0; nf < 16; nf++) {
            __half2 p0 = __floats2half2_rn(of[mg][nf][0] * inv0, of[mg][nf][1] * inv0);
            __half2 p1 = __floats2half2_rn(of[mg][nf][2] * inv1, of[mg][nf][3] * inv1);
            *(__half2*)(base + nf * 8)          = p0;
            *(__half2*)(base + 8 * Dd + nf * 8) = p1;
        }
    }
}

// ---------------------------------------------------------------------------
extern "C" void kernel_launch(void* const* d_in, const int* in_sizes, int n_in,
                              void* d_out, int out_size)
{
    const float* x     = (const float*)d_in[0];
    const float* w_qkv = (const float*)d_in[1];
    const float* b_qkv = (const float*)d_in[2];
    const float* w_out = (const float*)d_in[3];
    const float* b_out = (const float*)d_in[4];
    float* out = (float*)d_out;

    __half *qkvh, *xh, *wqt, *wot, *oh;
    cudaGetSymbolAddress((void**)&qkvh, g_qkvh);
    cudaGetSymbolAddress((void**)&xh,   g_xh);
    cudaGetSymbolAddress((void**)&wqt,  g_wqt);
    cudaGetSymbolAddress((void**)&wot,  g_wot);
    cudaGetSymbolAddress((void**)&oh,   g_oh);

    cudaFuncSetAttribute(gemm_fp16_kernel<true>,
                         cudaFuncAttributeMaxDynamicSharedMemorySize, GEMM_SMEM);
    cudaFuncSetAttribute(gemm_fp16_kernel<false>,
                         cudaFuncAttributeMaxDynamicSharedMemorySize, GEMM_SMEM);
    cudaFuncSetAttribute(attn_mma_kernel,
                         cudaFuncAttributeMaxDynamicSharedMemorySize, ATTN_SMEM);

    // 0) fused prep
    prep_kernel<<<PREP_GRID, 256>>>(x, xh, w_qkv, wqt, w_out, wot);

    // 1) QKV = X @ W_qkv + b_qkv  -> fp16
    gemm_fp16_kernel<true><<<dim3(3 * Dd / GBN, Mtot / GBM), 256, GEMM_SMEM>>>(
        xh, wqt, b_qkv, qkvh, 3 * Dd, Dd);

    // 2) attention (4 warps x m32, shared Q/V fragments) -> fp16 O
    attn_mma_kernel<<<dim3(Ll / 128, NHh, Bb), 128, ATTN_SMEM>>>(qkvh, oh);

    // 3) out = O @ W_out + b_out  -> fp32
    gemm_fp16_kernel<false><<<dim3(Dd / GBN, Mtot / GBM), 256, GEMM_SMEM>>>(
        oh, wot, b_out, out, Dd, Dd);
}